// round 8
// baseline (speedup 1.0000x reference)
#include <cuda_runtime.h>
#include <cuda_bf16.h>
#include <cstdint>

#define D        128
#define BLK      1024
#define THREADS  256
#define NROWS    262144

// w = exp(-max(d2,0)/25.6) = ex2(min(S*C2 + ci + cj, 0)), ci = -||xi||^2*log2e/25.6
#define C2       0.11271055f
#define SQSCALE  (-0.056355275f)

#define XSTR     272                   // Xi/Xj row stride bytes (128 bf16 + 16B pad)
#define WSTR     144                   // W row stride bytes (64 bf16 + 16B pad)

// smem layout
#define OFF_XIH  0
#define OFF_XIL  17408                 // 64*272
#define GRP_SZ   44032                 // XjH(17408) + XjL(17408) + W(9216)
#define GB0      34816
#define OFF_MB   (GB0 + GRP_SZ)       // merge buffer reuses group1 region (32768 <= 44032)
#define SM_TOTAL (GB0 + 2 * GRP_SZ)   // 122880

// ---------------- global scratch ----------------
__device__ float          g_sq[NROWS];                 // pre-scaled -||x||^2*log2e/25.6
__device__ __nv_bfloat16  g_xhi[(size_t)NROWS * D];
__device__ __nv_bfloat16  g_xlo[(size_t)NROWS * D];

// ---------------- PTX helpers ----------------
__device__ __forceinline__ uint32_t smem_u32(const void* p) {
    uint32_t a;
    asm("{ .reg .u64 t; cvta.to.shared.u64 t, %1; cvt.u32.u64 %0, t; }" : "=r"(a) : "l"(p));
    return a;
}
__device__ __forceinline__ void barg(int id) {
    asm volatile("bar.sync %0, %1;" :: "r"(id), "r"(128) : "memory");
}
__device__ __forceinline__ void ldsm4(uint32_t r[4], uint32_t addr) {
    asm volatile("ldmatrix.sync.aligned.m8n8.x4.shared.b16 {%0,%1,%2,%3}, [%4];"
                 : "=r"(r[0]), "=r"(r[1]), "=r"(r[2]), "=r"(r[3]) : "r"(addr));
}
__device__ __forceinline__ void ldsm4t(uint32_t r[4], uint32_t addr) {
    asm volatile("ldmatrix.sync.aligned.m8n8.x4.trans.shared.b16 {%0,%1,%2,%3}, [%4];"
                 : "=r"(r[0]), "=r"(r[1]), "=r"(r[2]), "=r"(r[3]) : "r"(addr));
}
__device__ __forceinline__ void mma16816(float c[4], const uint32_t a[4],
                                         uint32_t b0, uint32_t b1) {
    asm volatile("mma.sync.aligned.m16n8k16.row.col.f32.bf16.bf16.f32 "
                 "{%0,%1,%2,%3}, {%4,%5,%6,%7}, {%8,%9}, {%0,%1,%2,%3};"
                 : "+f"(c[0]), "+f"(c[1]), "+f"(c[2]), "+f"(c[3])
                 : "r"(a[0]), "r"(a[1]), "r"(a[2]), "r"(a[3]), "r"(b0), "r"(b1));
}
__device__ __forceinline__ float ex2(float e) {
    float r;
    asm("ex2.approx.f32 %0, %1;" : "=f"(r) : "f"(e));
    return r;
}
__device__ __forceinline__ uint32_t bf2u(__nv_bfloat162 h) {
    return *reinterpret_cast<uint32_t*>(&h);
}

// ---------------------------------------------------------------------------
// Prepass: fp32 -> bf16 hi/lo + pre-scaled row norms. One warp per row.
// ---------------------------------------------------------------------------
__global__ __launch_bounds__(256) void prep_kernel(const float4* __restrict__ x) {
    int row = blockIdx.x * 8 + (threadIdx.x >> 5);
    int l   = threadIdx.x & 31;
    float4 v = __ldg(&x[(size_t)row * 32 + l]);
    float s = v.x * v.x + v.y * v.y + v.z * v.z + v.w * v.w;
    #pragma unroll
    for (int o = 16; o; o >>= 1) s += __shfl_xor_sync(0xFFFFFFFFu, s, o);
    if (l == 0) g_sq[row] = s * SQSCALE;
    __nv_bfloat162 h01 = __floats2bfloat162_rn(v.x, v.y);
    __nv_bfloat162 h23 = __floats2bfloat162_rn(v.z, v.w);
    float2 f01 = __bfloat1622float2(h01);
    float2 f23 = __bfloat1622float2(h23);
    __nv_bfloat162 g01 = __floats2bfloat162_rn(v.x - f01.x, v.y - f01.y);
    __nv_bfloat162 g23 = __floats2bfloat162_rn(v.z - f23.x, v.w - f23.y);
    ((uint2*)g_xhi)[(size_t)row * 32 + l] = make_uint2(bf2u(h01), bf2u(h23));
    ((uint2*)g_xlo)[(size_t)row * 32 + l] = make_uint2(bf2u(g01), bf2u(g23));
}

// ---------------------------------------------------------------------------
// Ping-pong attention: CTA = 64 i-rows; 2 warpgroups alternate 64-row j-tiles.
// ---------------------------------------------------------------------------
__global__ __launch_bounds__(THREADS, 1)
void attn_kernel(float* __restrict__ out) {
    extern __shared__ char sm[];
    const uint32_t sb = smem_u32(sm);

    const int tid = threadIdx.x;
    const int wid = tid >> 5;
    const int l   = tid & 31;
    const int g   = wid >> 2;          // warpgroup 0/1
    const int wg  = wid & 3;           // warp within group
    const int wm  = wg >> 1;           // M half: rows [32wm, 32wm+32)
    const int wn  = wg & 1;            // N/D half
    const int tg  = tid & 127;
    const int cta  = blockIdx.x;
    const int blkI = cta >> 4, isub = cta & 15;
    const size_t rowbase = (size_t)blkI * BLK;
    const size_t irow0   = rowbase + (size_t)isub * 64;

    // lane patterns (R5-proven)
    const int rowA = l & 15;
    const int cA   = l >> 4;
    const int rowB = (l & 7) + ((l >> 4) << 3);
    const int cB   = (l >> 3) & 1;

    const uint32_t XJH = GB0 + (uint32_t)g * GRP_SZ;
    const uint32_t XJL = XJH + 17408;
    const uint32_t WOF = XJH + 34816;

    const uint32_t aXi  = (uint32_t)((32 * wm + rowA) * XSTR + cA * 16);        // Xi A (+4352/mt, +32/ks)
    const uint32_t bXj1 = (uint32_t)((32 * wn + rowB) * XSTR + cB * 16);        // G1 B (+4352/nt2, +32/ks)
    const uint32_t aW   = (uint32_t)((32 * wm + rowA) * WSTR + cA * 16);        // G2 A (+2304/mt, +32/ks2)
    const uint32_t bXj2 = (uint32_t)(rowA * XSTR + 128 * wn + cA * 16);         // G2 B (+4352/ks2, +32/dp)

    // ---- Xi tiles (whole CTA) ----
    {
        const uint4* gih = (const uint4*)(g_xhi + irow0 * D);
        const uint4* gil = (const uint4*)(g_xlo + irow0 * D);
        #pragma unroll
        for (int it = 0; it < 4; ++it) {
            int q = tid + it * 256;            // 0..1023
            int row = q >> 4, c = q & 15;
            *(uint4*)(sm + OFF_XIH + row * XSTR + c * 16) = __ldg(gih + q);
            *(uint4*)(sm + OFF_XIL + row * XSTR + c * 16) = __ldg(gil + q);
        }
    }
    // pre-scaled i-norms, direct LDG
    float civ[2][2];
    #pragma unroll
    for (int mt = 0; mt < 2; ++mt) {
        civ[mt][0] = __ldg(&g_sq[irow0 + 32 * wm + 16 * mt + (l >> 2)]);
        civ[mt][1] = __ldg(&g_sq[irow0 + 32 * wm + 16 * mt + 8 + (l >> 2)]);
    }
    __syncthreads();

    float acc2[2][8][4];
    #pragma unroll
    for (int mt = 0; mt < 2; ++mt)
        #pragma unroll
        for (int n = 0; n < 8; ++n)
            #pragma unroll
            for (int c = 0; c < 4; ++c) acc2[mt][n][c] = 0.0f;

    const int bid = 1 + g;

    for (int t = 0; t < 8; ++t) {
        const int jt = 2 * t + g;

        barg(bid);   // group's previous GEMM2 done -> Xj writable
        {
            const uint4* gjh = (const uint4*)(g_xhi + (rowbase + (size_t)jt * 64) * D);
            const uint4* gjl = (const uint4*)(g_xlo + (rowbase + (size_t)jt * 64) * D);
            #pragma unroll
            for (int it = 0; it < 8; ++it) {
                int q = tg + it * 128;          // 0..1023
                int row = q >> 4, c = q & 15;
                *(uint4*)(sm + XJH + row * XSTR + c * 16) = __ldg(gjh + q);
                *(uint4*)(sm + XJL + row * XSTR + c * 16) = __ldg(gjl + q);
            }
        }
        barg(bid);   // Xj ready

        // ---- GEMM1: S(32x32 per warp) = Xi . Xj^T, 3 combos ----
        float acc1[2][4][4];
        #pragma unroll
        for (int mt = 0; mt < 2; ++mt)
            #pragma unroll
            for (int n = 0; n < 4; ++n)
                #pragma unroll
                for (int c = 0; c < 4; ++c) acc1[mt][n][c] = 0.0f;

        #pragma unroll
        for (int ks = 0; ks < 8; ++ks) {
            uint32_t ah[2][4], al[2][4];
            #pragma unroll
            for (int mt = 0; mt < 2; ++mt) {
                ldsm4(ah[mt], sb + OFF_XIH + aXi + mt * 4352 + ks * 32);
                ldsm4(al[mt], sb + OFF_XIL + aXi + mt * 4352 + ks * 32);
            }
            #pragma unroll
            for (int nt2 = 0; nt2 < 2; ++nt2) {
                uint32_t bh[4], bl[4];
                ldsm4(bh, sb + XJH + bXj1 + nt2 * 4352 + ks * 32);
                ldsm4(bl, sb + XJL + bXj1 + nt2 * 4352 + ks * 32);
                #pragma unroll
                for (int mt = 0; mt < 2; ++mt) {
                    mma16816(acc1[mt][2 * nt2],     ah[mt], bh[0], bh[1]);
                    mma16816(acc1[mt][2 * nt2 + 1], ah[mt], bh[2], bh[3]);
                    mma16816(acc1[mt][2 * nt2],     al[mt], bh[0], bh[1]);
                    mma16816(acc1[mt][2 * nt2 + 1], al[mt], bh[2], bh[3]);
                    mma16816(acc1[mt][2 * nt2],     ah[mt], bl[0], bl[1]);
                    mma16816(acc1[mt][2 * nt2 + 1], ah[mt], bl[2], bl[3]);
                }
            }
        }

        // ---- epilogue: w = ex2(min(S*C2 + ci + cj, 0)) -> W(g) ----
        {
            const float2* sq2 = (const float2*)(g_sq + rowbase + (size_t)jt * 64);
            #pragma unroll
            for (int n = 0; n < 4; ++n) {
                float2 cj = __ldg(&sq2[16 * wn + 4 * n + (l & 3)]);
                #pragma unroll
                for (int mt = 0; mt < 2; ++mt) {
                    const float* c = acc1[mt][n];
                    float w0 = ex2(fminf(fmaf(c[0], C2, civ[mt][0] + cj.x), 0.0f));
                    float w1 = ex2(fminf(fmaf(c[1], C2, civ[mt][0] + cj.y), 0.0f));
                    float w2 = ex2(fminf(fmaf(c[2], C2, civ[mt][1] + cj.x), 0.0f));
                    float w3 = ex2(fminf(fmaf(c[3], C2, civ[mt][1] + cj.y), 0.0f));
                    uint32_t wa = (uint32_t)((32 * wm + 16 * mt + (l >> 2)) * WSTR
                                             + 64 * wn + 16 * n + 4 * (l & 3));
                    *(uint32_t*)(sm + WOF + wa)            = bf2u(__floats2bfloat162_rn(w0, w1));
                    *(uint32_t*)(sm + WOF + wa + 8 * WSTR) = bf2u(__floats2bfloat162_rn(w2, w3));
                }
            }
        }
        barg(bid);   // W ready

        // ---- GEMM2: acc2(32x64 per warp) += W . Xj, 2 combos, K=64 ----
        #pragma unroll
        for (int ks2 = 0; ks2 < 4; ++ks2) {
            uint32_t wf[2][4];
            #pragma unroll
            for (int mt = 0; mt < 2; ++mt)
                ldsm4(wf[mt], sb + WOF + aW + mt * 2304 + ks2 * 32);
            #pragma unroll
            for (int dp = 0; dp < 4; ++dp) {
                uint32_t bh[4], bl[4];
                ldsm4t(bh, sb + XJH + bXj2 + ks2 * 4352 + dp * 32);
                ldsm4t(bl, sb + XJL + bXj2 + ks2 * 4352 + dp * 32);
                #pragma unroll
                for (int mt = 0; mt < 2; ++mt) {
                    mma16816(acc2[mt][2 * dp],     wf[mt], bh[0], bh[1]);
                    mma16816(acc2[mt][2 * dp + 1], wf[mt], bh[2], bh[3]);
                    mma16816(acc2[mt][2 * dp],     wf[mt], bl[0], bl[1]);
                    mma16816(acc2[mt][2 * dp + 1], wf[mt], bl[2], bl[3]);
                }
            }
        }
    }

    // ---- merge group partials, write out ----
    float* mb = (float*)(sm + OFF_MB);
    if (g == 1) {
        #pragma unroll
        for (int mt = 0; mt < 2; ++mt)
            #pragma unroll
            for (int n = 0; n < 8; ++n) {
                int row = 32 * wm + 16 * mt + (l >> 2);
                int col = 64 * wn + 8 * n + 2 * (l & 3);
                *(float2*)(mb + row * 128 + col)       = make_float2(acc2[mt][n][0], acc2[mt][n][1]);
                *(float2*)(mb + (row + 8) * 128 + col) = make_float2(acc2[mt][n][2], acc2[mt][n][3]);
            }
    }
    __syncthreads();
    if (g == 0) {
        const float sc = 1.0f / (float)BLK;
        #pragma unroll
        for (int mt = 0; mt < 2; ++mt)
            #pragma unroll
            for (int n = 0; n < 8; ++n) {
                int row = 32 * wm + 16 * mt + (l >> 2);
                int col = 64 * wn + 8 * n + 2 * (l & 3);
                float2 v0 = *(float2*)(mb + row * 128 + col);
                float2 v1 = *(float2*)(mb + (row + 8) * 128 + col);
                float* o0 = out + (irow0 + row) * D + col;
                float* o1 = out + (irow0 + row + 8) * D + col;
                *(float2*)o0 = make_float2((acc2[mt][n][0] + v0.x) * sc, (acc2[mt][n][1] + v0.y) * sc);
                *(float2*)o1 = make_float2((acc2[mt][n][2] + v1.x) * sc, (acc2[mt][n][3] + v1.y) * sc);
            }
    }
}

// ---------------------------------------------------------------------------
extern "C" void kernel_launch(void* const* d_in, const int* in_sizes, int n_in,
                              void* d_out, int out_size) {
    const float* x = (const float*)d_in[0];
    float* out = (float*)d_out;
    const int nrows = in_sizes[0] / D;

    static bool attr_set = false;
    if (!attr_set) {
        cudaFuncSetAttribute(attn_kernel,
                             cudaFuncAttributeMaxDynamicSharedMemorySize, SM_TOTAL);
        attr_set = true;
    }
    prep_kernel<<<nrows / 8, 256>>>((const float4*)x);
    attn_kernel<<<nrows / 64, THREADS, SM_TOTAL>>>(out);
}

// round 10
// speedup vs baseline: 1.0434x; 1.0434x over previous
#include <cuda_runtime.h>
#include <cuda_bf16.h>
#include <cstdint>

#define D        128
#define BLK      1024
#define THREADS  256
#define NROWS    262144

// w = ex2(min(S*C2 + ci + cj, 0)), ci = -||xi||^2*log2e/25.6 (pre-scaled in prep)
#define C2       0.11271055f
#define SQSCALE  (-0.056355275f)

#define RSB      272                   // proven padded row stride (bytes)

// smem layout (bytes)
#define OFF_XIH  0                     // 64 x RSB
#define OFF_XIL  17408
#define OFF_W    34816                 // 64 x RSB, cols = j (128 bf16)
#define OFF_XJ   52224                 // 2 buffers x (XjH + XjL), 128 x RSB each
#define BUF_SZ   69632                 // 2 * 34816
#define SM_TOTAL (OFF_XJ + 2 * BUF_SZ) // 191488

// ---------------- global scratch ----------------
__device__ float          g_sq[NROWS];                 // pre-scaled
__device__ __nv_bfloat16  g_xhi[(size_t)NROWS * D];
__device__ __nv_bfloat16  g_xlo[(size_t)NROWS * D];

// ---------------- PTX helpers ----------------
__device__ __forceinline__ uint32_t smem_u32(const void* p) {
    uint32_t a;
    asm("{ .reg .u64 t; cvta.to.shared.u64 t, %1; cvt.u32.u64 %0, t; }" : "=r"(a) : "l"(p));
    return a;
}
__device__ __forceinline__ void cpa16(uint32_t dst, const void* src) {
    asm volatile("cp.async.cg.shared.global [%0], [%1], 16;" :: "r"(dst), "l"(src));
}
#define CP_COMMIT() asm volatile("cp.async.commit_group;" ::: "memory")
#define CP_WAIT0()  asm volatile("cp.async.wait_group 0;" ::: "memory")

__device__ __forceinline__ void ldsm4(uint32_t r[4], uint32_t addr) {
    asm volatile("ldmatrix.sync.aligned.m8n8.x4.shared.b16 {%0,%1,%2,%3}, [%4];"
                 : "=r"(r[0]), "=r"(r[1]), "=r"(r[2]), "=r"(r[3]) : "r"(addr));
}
__device__ __forceinline__ void ldsm4t(uint32_t r[4], uint32_t addr) {
    asm volatile("ldmatrix.sync.aligned.m8n8.x4.trans.shared.b16 {%0,%1,%2,%3}, [%4];"
                 : "=r"(r[0]), "=r"(r[1]), "=r"(r[2]), "=r"(r[3]) : "r"(addr));
}
__device__ __forceinline__ void mma16816(float c[4], const uint32_t a[4],
                                         uint32_t b0, uint32_t b1) {
    asm volatile("mma.sync.aligned.m16n8k16.row.col.f32.bf16.bf16.f32 "
                 "{%0,%1,%2,%3}, {%4,%5,%6,%7}, {%8,%9}, {%0,%1,%2,%3};"
                 : "+f"(c[0]), "+f"(c[1]), "+f"(c[2]), "+f"(c[3])
                 : "r"(a[0]), "r"(a[1]), "r"(a[2]), "r"(a[3]), "r"(b0), "r"(b1));
}
__device__ __forceinline__ float ex2(float e) {
    float r;
    asm("ex2.approx.f32 %0, %1;" : "=f"(r) : "f"(e));
    return r;
}
__device__ __forceinline__ uint32_t bf2u(__nv_bfloat162 h) {
    return *reinterpret_cast<uint32_t*>(&h);
}

// ---------------------------------------------------------------------------
// Prepass: fp32 -> bf16 hi/lo + pre-scaled row norms. One warp per row.
// ---------------------------------------------------------------------------
__global__ __launch_bounds__(256) void prep_kernel(const float4* __restrict__ x) {
    int row = blockIdx.x * 8 + (threadIdx.x >> 5);
    int l   = threadIdx.x & 31;
    float4 v = __ldg(&x[(size_t)row * 32 + l]);
    float s = v.x * v.x + v.y * v.y + v.z * v.z + v.w * v.w;
    #pragma unroll
    for (int o = 16; o; o >>= 1) s += __shfl_xor_sync(0xFFFFFFFFu, s, o);
    if (l == 0) g_sq[row] = s * SQSCALE;
    __nv_bfloat162 h01 = __floats2bfloat162_rn(v.x, v.y);
    __nv_bfloat162 h23 = __floats2bfloat162_rn(v.z, v.w);
    float2 f01 = __bfloat1622float2(h01);
    float2 f23 = __bfloat1622float2(h23);
    __nv_bfloat162 g01 = __floats2bfloat162_rn(v.x - f01.x, v.y - f01.y);
    __nv_bfloat162 g23 = __floats2bfloat162_rn(v.z - f23.x, v.w - f23.y);
    ((uint2*)g_xhi)[(size_t)row * 32 + l] = make_uint2(bf2u(h01), bf2u(h23));
    ((uint2*)g_xlo)[(size_t)row * 32 + l] = make_uint2(bf2u(g01), bf2u(g23));
}

// issue cp.async for one 128x128 bf16 tile pair (hi+lo), padded-272 layout
__device__ __forceinline__ void issue_xj(uint32_t sbH, uint32_t sbL,
                                         const char* gh, const char* gl, int tid) {
    #pragma unroll
    for (int it = 0; it < 8; ++it) {
        int q   = tid + it * 256;            // 0..2047 16B chunks
        int row = q >> 4, c16 = q & 15;
        uint32_t d = (uint32_t)(row * RSB + c16 * 16);
        cpa16(sbH + d, gh + (size_t)q * 16);
        cpa16(sbL + d, gl + (size_t)q * 16);
    }
}

// ---------------------------------------------------------------------------
// Fused attention: CTA = 64 i-rows; cp.async double-buffered 128-row j-tiles.
// Warp grid: wm (0..1) = 32 i-rows; wn (0..3) = 32 j-cols (G1) / 32 d-cols (G2).
// ---------------------------------------------------------------------------
__global__ __launch_bounds__(THREADS, 1)
void attn_kernel(float* __restrict__ out) {
    extern __shared__ char sm[];
    const uint32_t sb = smem_u32(sm);

    const int tid = threadIdx.x;
    const int wid = tid >> 5;
    const int l   = tid & 31;
    const int wm  = wid >> 2;          // 0..1
    const int wn  = wid & 3;           // 0..3
    const int cta  = blockIdx.x;
    const int blkI = cta >> 4, isub = cta & 15;
    const size_t rowbase = (size_t)blkI * BLK;
    const size_t irow0   = rowbase + (size_t)isub * 64;

    // lane patterns (proven)
    const int rowA = l & 15;
    const int colA = l >> 4;
    const int rowB = (l & 7) + ((l >> 4) << 3);
    const int colB = (l >> 3) & 1;

    const uint32_t aXi = (uint32_t)((32 * wm + rowA) * RSB + colA * 16);  // +4352/mt, +32/ks
    const uint32_t bXj = (uint32_t)((32 * wn + rowB) * RSB + colB * 16);  // +4352/nt2, +32/ks
    const uint32_t aW  = (uint32_t)((32 * wm + rowA) * RSB + colA * 16);  // W same shape
    const uint32_t bT  = (uint32_t)(rowA * RSB + colA * 16 + 64 * wn);    // +4352/ks2, +32/dp

    const char* ghb = (const char*)(g_xhi + rowbase * D);
    const char* glb = (const char*)(g_xlo + rowbase * D);

    // ---- prologue: Xi tiles (cp.async) + Xj0 prefetch ----
    {
        const char* gih = (const char*)(g_xhi + irow0 * D);
        const char* gil = (const char*)(g_xlo + irow0 * D);
        #pragma unroll
        for (int it = 0; it < 4; ++it) {
            int q   = tid + it * 256;        // 0..1023 chunks (64 rows x 16)
            int row = q >> 4, c16 = q & 15;
            uint32_t d = (uint32_t)(row * RSB + c16 * 16);
            cpa16(sb + OFF_XIH + d, gih + (size_t)q * 16);
            cpa16(sb + OFF_XIL + d, gil + (size_t)q * 16);
        }
    }
    issue_xj(sb + OFF_XJ, sb + OFF_XJ + 34816, ghb, glb, tid);
    CP_COMMIT();

    // i-norms (pre-scaled), direct LDG
    float civ[2][2];
    #pragma unroll
    for (int mt = 0; mt < 2; ++mt) {
        civ[mt][0] = __ldg(&g_sq[irow0 + 32 * wm + 16 * mt + (l >> 2)]);
        civ[mt][1] = __ldg(&g_sq[irow0 + 32 * wm + 16 * mt + 8 + (l >> 2)]);
    }

    float acc2[2][4][4];
    #pragma unroll
    for (int mt = 0; mt < 2; ++mt)
        #pragma unroll
        for (int n = 0; n < 4; ++n)
            #pragma unroll
            for (int c = 0; c < 4; ++c) acc2[mt][n][c] = 0.0f;

    CP_WAIT0();
    __syncthreads();

    for (int jt = 0; jt < 8; ++jt) {
        const uint32_t XJH = sb + OFF_XJ + (uint32_t)(jt & 1) * BUF_SZ;
        const uint32_t XJL = XJH + 34816;

        // prefetch next j-tile into the other buffer (its readers done last iter)
        if (jt < 7) {
            uint32_t PH = sb + OFF_XJ + (uint32_t)((jt & 1) ^ 1) * BUF_SZ;
            issue_xj(PH, PH + 34816,
                     ghb + (size_t)(jt + 1) * 32768, glb + (size_t)(jt + 1) * 32768, tid);
            CP_COMMIT();
        }

        // ---- GEMM1: S(32x32/warp) = Xi . Xj^T, 3 combos ----
        float acc1[2][4][4];
        #pragma unroll
        for (int mt = 0; mt < 2; ++mt)
            #pragma unroll
            for (int n = 0; n < 4; ++n)
                #pragma unroll
                for (int c = 0; c < 4; ++c) acc1[mt][n][c] = 0.0f;

        #pragma unroll
        for (int ks = 0; ks < 8; ++ks) {
            uint32_t ah[2][4], al[2][4];
            #pragma unroll
            for (int mt = 0; mt < 2; ++mt) {
                ldsm4(ah[mt], sb + OFF_XIH + aXi + mt * 4352 + ks * 32);
                ldsm4(al[mt], sb + OFF_XIL + aXi + mt * 4352 + ks * 32);
            }
            #pragma unroll
            for (int nt2 = 0; nt2 < 2; ++nt2) {
                uint32_t bh[4], bl[4];
                ldsm4(bh, XJH + bXj + nt2 * 4352 + ks * 32);
                ldsm4(bl, XJL + bXj + nt2 * 4352 + ks * 32);
                #pragma unroll
                for (int mt = 0; mt < 2; ++mt) {
                    mma16816(acc1[mt][2 * nt2],     ah[mt], bh[0], bh[1]);
                    mma16816(acc1[mt][2 * nt2 + 1], ah[mt], bh[2], bh[3]);
                    mma16816(acc1[mt][2 * nt2],     al[mt], bh[0], bh[1]);
                    mma16816(acc1[mt][2 * nt2 + 1], al[mt], bh[2], bh[3]);
                    mma16816(acc1[mt][2 * nt2],     ah[mt], bl[0], bl[1]);
                    mma16816(acc1[mt][2 * nt2 + 1], ah[mt], bl[2], bl[3]);
                }
            }
        }

        // ---- epilogue: w = ex2(min(S*C2+ci+cj,0)) -> W (bf16, [i64][j128]) ----
        {
            const float2* cjp = (const float2*)(g_sq + rowbase + (size_t)jt * 128);
            #pragma unroll
            for (int n = 0; n < 4; ++n) {
                float2 cj = __ldg(&cjp[(32 * wn + 8 * n) / 2 + (l & 3)]);
                #pragma unroll
                for (int mt = 0; mt < 2; ++mt) {
                    const float* c = acc1[mt][n];
                    float w0 = ex2(fminf(fmaf(c[0], C2, civ[mt][0] + cj.x), 0.0f));
                    float w1 = ex2(fminf(fmaf(c[1], C2, civ[mt][0] + cj.y), 0.0f));
                    float w2 = ex2(fminf(fmaf(c[2], C2, civ[mt][1] + cj.x), 0.0f));
                    float w3 = ex2(fminf(fmaf(c[3], C2, civ[mt][1] + cj.y), 0.0f));
                    uint32_t wa = (uint32_t)((32 * wm + 16 * mt + (l >> 2)) * RSB
                                             + (32 * wn + 8 * n + 2 * (l & 3)) * 2);
                    *(uint32_t*)(sm + OFF_W + wa)           = bf2u(__floats2bfloat162_rn(w0, w1));
                    *(uint32_t*)(sm + OFF_W + wa + 8 * RSB) = bf2u(__floats2bfloat162_rn(w2, w3));
                }
            }
        }
        __syncthreads();   // W complete

        // ---- GEMM2: acc2(32x32/warp) += W . Xj  (2 combos, K=128) ----
        #pragma unroll
        for (int ks2 = 0; ks2 < 8; ++ks2) {
            uint32_t wf[2][4];
            #pragma unroll
            for (int mt = 0; mt < 2; ++mt)
                ldsm4(wf[mt], sb + OFF_W + aW + mt * 4352 + ks2 * 32);
            #pragma unroll
            for (int dp = 0; dp < 2; ++dp) {
                uint32_t bh[4], bl[4];
                ldsm4t(bh, XJH + bT + ks2 * 4352 + dp * 32);
                ldsm4t(bl, XJL + bT + ks2 * 4352 + dp * 32);
                #pragma unroll
                for (int mt = 0; mt < 2; ++mt) {
                    mma16816(acc2[mt][2 * dp],     wf[mt], bh[0], bh[1]);
                    mma16816(acc2[mt][2 * dp + 1], wf[mt], bh[2], bh[3]);
                    mma16816(acc2[mt][2 * dp],     wf[mt], bl[0], bl[1]);
                    mma16816(acc2[mt][2 * dp + 1], wf[mt], bl[2], bl[3]);
                }
            }
        }

        CP_WAIT0();        // next buffer landed
        __syncthreads();   // all GEMM readers done; W writable; buffer swap safe
    }

    // ---- write out (scale 1/1024) ----
    const float sc = 1.0f / (float)BLK;
    #pragma unroll
    for (int mt = 0; mt < 2; ++mt) {
        const size_t r0 = irow0 + 32 * wm + 16 * mt + (l >> 2);
        #pragma unroll
        for (int n = 0; n < 4; ++n) {
            const int col = 32 * wn + 8 * n + 2 * (l & 3);
            *(float2*)(out + r0 * D + col)       = make_float2(acc2[mt][n][0] * sc, acc2[mt][n][1] * sc);
            *(float2*)(out + (r0 + 8) * D + col) = make_float2(acc2[mt][n][2] * sc, acc2[mt][n][3] * sc);
        }
    }
}

// ---------------------------------------------------------------------------
extern "C" void kernel_launch(void* const* d_in, const int* in_sizes, int n_in,
                              void* d_out, int out_size) {
    const float* x = (const float*)d_in[0];
    float* out = (float*)d_out;
    const int nrows = in_sizes[0] / D;

    static bool attr_set = false;
    if (!attr_set) {
        cudaFuncSetAttribute(attn_kernel,
                             cudaFuncAttributeMaxDynamicSharedMemorySize, SM_TOTAL);
        attr_set = true;
    }
    prep_kernel<<<nrows / 8, 256>>>((const float4*)x);
    attn_kernel<<<nrows / 64, THREADS, SM_TOTAL>>>(out);
}

// round 11
// speedup vs baseline: 1.2058x; 1.1557x over previous
#include <cuda_runtime.h>
#include <cuda_bf16.h>
#include <cstdint>

#define D        128
#define BLK      1024
#define THREADS  256
#define NROWS    262144

// w = ex2(min(S*C2 + ci + cj, 0)), ci = -||xi||^2*log2e/25.6 (pre-scaled in prep)
#define C2       0.11271055f
#define SQSCALE  (-0.056355275f)

// ---- smem: XOR-swizzled 256B-row tiles, 32KB each ----
#define TILE     32768
#define OFF_XIH  0
#define OFF_XIL  32768
#define OFF_W    65536
#define OFF_XJ   98304                 // 2 x (XjH + XjL)
#define BUF_SZ   65536
#define SM_TOTAL (OFF_XJ + 2 * BUF_SZ) // 229376

// ---------------- global scratch ----------------
__device__ float          g_sq[NROWS];                 // pre-scaled
__device__ __nv_bfloat16  g_xhi[(size_t)NROWS * D];
__device__ __nv_bfloat16  g_xlo[(size_t)NROWS * D];

// ---------------- PTX helpers ----------------
__device__ __forceinline__ uint32_t smem_u32(const void* p) {
    uint32_t a;
    asm("{ .reg .u64 t; cvta.to.shared.u64 t, %1; cvt.u32.u64 %0, t; }" : "=r"(a) : "l"(p));
    return a;
}
__device__ __forceinline__ void cpa16(uint32_t dst, const void* src) {
    asm volatile("cp.async.cg.shared.global [%0], [%1], 16;" :: "r"(dst), "l"(src));
}
#define CP_COMMIT() asm volatile("cp.async.commit_group;" ::: "memory")
#define CP_WAIT0()  asm volatile("cp.async.wait_group 0;" ::: "memory")

__device__ __forceinline__ void ldsm4(uint32_t r[4], uint32_t addr) {
    asm volatile("ldmatrix.sync.aligned.m8n8.x4.shared.b16 {%0,%1,%2,%3}, [%4];"
                 : "=r"(r[0]), "=r"(r[1]), "=r"(r[2]), "=r"(r[3]) : "r"(addr));
}
__device__ __forceinline__ void ldsm4t(uint32_t r[4], uint32_t addr) {
    asm volatile("ldmatrix.sync.aligned.m8n8.x4.trans.shared.b16 {%0,%1,%2,%3}, [%4];"
                 : "=r"(r[0]), "=r"(r[1]), "=r"(r[2]), "=r"(r[3]) : "r"(addr));
}
__device__ __forceinline__ void mma16816(float c[4], const uint32_t a[4],
                                         uint32_t b0, uint32_t b1) {
    asm volatile("mma.sync.aligned.m16n8k16.row.col.f32.bf16.bf16.f32 "
                 "{%0,%1,%2,%3}, {%4,%5,%6,%7}, {%8,%9}, {%0,%1,%2,%3};"
                 : "+f"(c[0]), "+f"(c[1]), "+f"(c[2]), "+f"(c[3])
                 : "r"(a[0]), "r"(a[1]), "r"(a[2]), "r"(a[3]), "r"(b0), "r"(b1));
}
__device__ __forceinline__ float ex2(float e) {
    float r;
    asm("ex2.approx.f32 %0, %1;" : "=f"(r) : "f"(e));
    return r;
}
__device__ __forceinline__ uint32_t bf2u(__nv_bfloat162 h) {
    return *reinterpret_cast<uint32_t*>(&h);
}

// ---------------------------------------------------------------------------
// Prepass: fp32 -> bf16 hi/lo + pre-scaled row norms. One warp per row.
// ---------------------------------------------------------------------------
__global__ __launch_bounds__(256) void prep_kernel(const float4* __restrict__ x) {
    int row = blockIdx.x * 8 + (threadIdx.x >> 5);
    int l   = threadIdx.x & 31;
    float4 v = __ldg(&x[(size_t)row * 32 + l]);
    float s = v.x * v.x + v.y * v.y + v.z * v.z + v.w * v.w;
    #pragma unroll
    for (int o = 16; o; o >>= 1) s += __shfl_xor_sync(0xFFFFFFFFu, s, o);
    if (l == 0) g_sq[row] = s * SQSCALE;
    __nv_bfloat162 h01 = __floats2bfloat162_rn(v.x, v.y);
    __nv_bfloat162 h23 = __floats2bfloat162_rn(v.z, v.w);
    float2 f01 = __bfloat1622float2(h01);
    float2 f23 = __bfloat1622float2(h23);
    __nv_bfloat162 g01 = __floats2bfloat162_rn(v.x - f01.x, v.y - f01.y);
    __nv_bfloat162 g23 = __floats2bfloat162_rn(v.z - f23.x, v.w - f23.y);
    ((uint2*)g_xhi)[(size_t)row * 32 + l] = make_uint2(bf2u(h01), bf2u(h23));
    ((uint2*)g_xlo)[(size_t)row * 32 + l] = make_uint2(bf2u(g01), bf2u(g23));
}

// cp.async one 128x128 bf16 tile pair (hi+lo) into swizzled smem.
// swizzle: physical_chunk = c16 ^ (row & 7)
__device__ __forceinline__ void issue_tile(uint32_t dH, uint32_t dL,
                                           const char* gh, const char* gl, int tid) {
    #pragma unroll
    for (int it = 0; it < 8; ++it) {
        int q   = tid + it * 256;            // 0..2047 16B chunks
        int row = q >> 4, c16 = q & 15;
        uint32_t dsw = (uint32_t)((row << 8) + ((c16 ^ (row & 7)) << 4));
        cpa16(dH + dsw, gh + (size_t)q * 16);
        cpa16(dL + dsw, gl + (size_t)q * 16);
    }
}

// ---------------------------------------------------------------------------
// Fused attention: 128-row CTA (R7 tiling), swizzled smem, cp.async DB.
// ---------------------------------------------------------------------------
__global__ __launch_bounds__(THREADS, 1)
void attn_kernel(float* __restrict__ out) {
    extern __shared__ char sm[];
    const uint32_t sb = smem_u32(sm);

    const int tid = threadIdx.x;
    const int wid = tid >> 5;
    const int l   = tid & 31;
    const int wm  = wid >> 1;        // 0..3: rows [32wm, 32wm+32)
    const int wn  = wid & 1;         // 0..1: cols [64wn, 64wn+64)
    const int cta  = blockIdx.x;
    const int blkI = cta >> 3, isub = cta & 7;
    const size_t rowbase = (size_t)blkI * BLK;
    const size_t irow0   = rowbase + (size_t)isub * 128;

    const int ph  = l & 7;           // LDSM swizzle phase (= provided row & 7)
    const int rph = (l >> 2) & 7;    // epilogue store phase (= stored row & 7)
    const int cA  = l >> 4;          // 16B half-column for A-style / trans
    const int cB  = (l >> 3) & 1;    // for non-trans B

    // lane base row offsets (bytes; row stride 256)
    const uint32_t aRow  = (uint32_t)((32 * wm + (l & 15)) << 8);                  // A-style (+4096/mt)
    const uint32_t b1Row = (uint32_t)((64 * wn + (l & 7) + ((l >> 4) << 3)) << 8); // B non-trans (+4096/nt2)
    const uint32_t b2Row = (uint32_t)((l & 15) << 8);                              // B trans (+4096/ks)

    const char* ghb = (const char*)(g_xhi + rowbase * D);
    const char* glb = (const char*)(g_xlo + rowbase * D);

    // ---- prologue: Xi tiles + Xj0 via cp.async ----
    issue_tile(sb + OFF_XIH, sb + OFF_XIL,
               (const char*)(g_xhi + irow0 * D), (const char*)(g_xlo + irow0 * D), tid);
    issue_tile(sb + OFF_XJ, sb + OFF_XJ + TILE, ghb, glb, tid);
    CP_COMMIT();

    // pre-scaled i-norms, direct LDG (L2-hot)
    float civ[2][2];
    #pragma unroll
    for (int mt = 0; mt < 2; ++mt) {
        civ[mt][0] = __ldg(&g_sq[irow0 + 32 * wm + 16 * mt + (l >> 2)]);
        civ[mt][1] = __ldg(&g_sq[irow0 + 32 * wm + 16 * mt + 8 + (l >> 2)]);
    }

    float acc2[2][8][4];
    #pragma unroll
    for (int mt = 0; mt < 2; ++mt)
        #pragma unroll
        for (int nt = 0; nt < 8; ++nt)
            #pragma unroll
            for (int c = 0; c < 4; ++c) acc2[mt][nt][c] = 0.0f;

    CP_WAIT0();
    __syncthreads();

    for (int jt = 0; jt < 8; ++jt) {
        const uint32_t XJH = sb + OFF_XJ + (uint32_t)(jt & 1) * BUF_SZ;
        const uint32_t XJL = XJH + TILE;

        // prefetch next j-tile into the other buffer (readers done at jt-1's bottom sync)
        if (jt < 7) {
            uint32_t PH = sb + OFF_XJ + (uint32_t)((jt & 1) ^ 1) * BUF_SZ;
            issue_tile(PH, PH + TILE,
                       ghb + (size_t)(jt + 1) * 32768, glb + (size_t)(jt + 1) * 32768, tid);
            CP_COMMIT();
        }

        // ---- GEMM1: S(32x64) = Xi . Xj^T, 3 combos ----
        float acc1[2][8][4];
        #pragma unroll
        for (int mt = 0; mt < 2; ++mt)
            #pragma unroll
            for (int nt = 0; nt < 8; ++nt)
                #pragma unroll
                for (int c = 0; c < 4; ++c) acc1[mt][nt][c] = 0.0f;

        #pragma unroll
        for (int ks = 0; ks < 8; ++ks) {
            const uint32_t ca = (uint32_t)(((2 * ks + cA) ^ ph) << 4);
            const uint32_t cb = (uint32_t)(((2 * ks + cB) ^ ph) << 4);
            uint32_t ah[2][4], al[2][4];
            #pragma unroll
            for (int mt = 0; mt < 2; ++mt) {
                ldsm4(ah[mt], sb + OFF_XIH + aRow + mt * 4096 + ca);
                ldsm4(al[mt], sb + OFF_XIL + aRow + mt * 4096 + ca);
            }
            #pragma unroll
            for (int nt2 = 0; nt2 < 4; ++nt2) {
                uint32_t bh[4], bl[4];
                ldsm4(bh, XJH + b1Row + nt2 * 4096 + cb);
                ldsm4(bl, XJL + b1Row + nt2 * 4096 + cb);
                #pragma unroll
                for (int mt = 0; mt < 2; ++mt) {
                    mma16816(acc1[mt][2 * nt2],     ah[mt], bh[0], bh[1]);
                    mma16816(acc1[mt][2 * nt2 + 1], ah[mt], bh[2], bh[3]);
                    mma16816(acc1[mt][2 * nt2],     al[mt], bh[0], bh[1]);
                    mma16816(acc1[mt][2 * nt2 + 1], al[mt], bh[2], bh[3]);
                    mma16816(acc1[mt][2 * nt2],     ah[mt], bl[0], bl[1]);
                    mma16816(acc1[mt][2 * nt2 + 1], ah[mt], bl[2], bl[3]);
                }
            }
        }

        // ---- epilogue: w = ex2(min(S*C2 + ci + cj, 0)) -> swizzled W tile ----
        {
            const float2* cjp = (const float2*)(g_sq + rowbase + (size_t)jt * 128);
            #pragma unroll
            for (int nt = 0; nt < 8; ++nt) {
                float2 cj = __ldg(&cjp[32 * wn + 4 * nt + (l & 3)]);
                const uint32_t wcol = (uint32_t)((((8 * wn + nt) ^ rph) << 4) + ((l & 3) << 2));
                #pragma unroll
                for (int mt = 0; mt < 2; ++mt) {
                    const float* c = acc1[mt][nt];
                    float w0 = ex2(fminf(fmaf(c[0], C2, civ[mt][0] + cj.x), 0.0f));
                    float w1 = ex2(fminf(fmaf(c[1], C2, civ[mt][0] + cj.y), 0.0f));
                    float w2 = ex2(fminf(fmaf(c[2], C2, civ[mt][1] + cj.x), 0.0f));
                    float w3 = ex2(fminf(fmaf(c[3], C2, civ[mt][1] + cj.y), 0.0f));
                    const uint32_t wr = (uint32_t)((32 * wm + 16 * mt + (l >> 2)) << 8);
                    *(uint32_t*)(sm + OFF_W + wr + wcol)        = bf2u(__floats2bfloat162_rn(w0, w1));
                    *(uint32_t*)(sm + OFF_W + wr + 2048 + wcol) = bf2u(__floats2bfloat162_rn(w2, w3));
                }
            }
        }
        __syncthreads();   // W complete

        // ---- GEMM2: acc2(32x64) += W . Xj  (Whi*Xhi + Whi*Xlo) ----
        #pragma unroll
        for (int ks = 0; ks < 8; ++ks) {
            const uint32_t ca = (uint32_t)(((2 * ks + cA) ^ ph) << 4);
            uint32_t wh[2][4];
            #pragma unroll
            for (int mt = 0; mt < 2; ++mt)
                ldsm4(wh[mt], sb + OFF_W + aRow + mt * 4096 + ca);
            #pragma unroll
            for (int dp = 0; dp < 4; ++dp) {
                const uint32_t cb2 = (uint32_t)(((8 * wn + 2 * dp + cA) ^ ph) << 4);
                uint32_t bh[4], bl[4];
                ldsm4t(bh, XJH + b2Row + ks * 4096 + cb2);
                ldsm4t(bl, XJL + b2Row + ks * 4096 + cb2);
                #pragma unroll
                for (int mt = 0; mt < 2; ++mt) {
                    mma16816(acc2[mt][2 * dp],     wh[mt], bh[0], bh[1]);
                    mma16816(acc2[mt][2 * dp + 1], wh[mt], bh[2], bh[3]);
                    mma16816(acc2[mt][2 * dp],     wh[mt], bl[0], bl[1]);
                    mma16816(acc2[mt][2 * dp + 1], wh[mt], bl[2], bl[3]);
                }
            }
        }

        CP_WAIT0();        // next buffer landed
        __syncthreads();   // readers done; W writable; buffer swap safe
    }

    // ---- write out (scale 1/1024) ----
    const float sc = 1.0f / (float)BLK;
    #pragma unroll
    for (int mt = 0; mt < 2; ++mt) {
        const size_t r0 = irow0 + 32 * wm + 16 * mt + (l >> 2);
        #pragma unroll
        for (int nt = 0; nt < 8; ++nt) {
            const int col = 64 * wn + 8 * nt + 2 * (l & 3);
            *(float2*)(out + r0 * D + col)       = make_float2(acc2[mt][nt][0] * sc, acc2[mt][nt][1] * sc);
            *(float2*)(out + (r0 + 8) * D + col) = make_float2(acc2[mt][nt][2] * sc, acc2[mt][nt][3] * sc);
        }
    }
}

// ---------------------------------------------------------------------------
extern "C" void kernel_launch(void* const* d_in, const int* in_sizes, int n_in,
                              void* d_out, int out_size) {
    const float* x = (const float*)d_in[0];
    float* out = (float*)d_out;
    const int nrows = in_sizes[0] / D;

    static bool attr_set = false;
    if (!attr_set) {
        cudaFuncSetAttribute(attn_kernel,
                             cudaFuncAttributeMaxDynamicSharedMemorySize, SM_TOTAL);
        attr_set = true;
    }
    prep_kernel<<<nrows / 8, 256>>>((const float4*)x);
    attn_kernel<<<nrows / 128, THREADS, SM_TOTAL>>>(out);
}

// round 12
// speedup vs baseline: 1.2950x; 1.0739x over previous
#include <cuda_runtime.h>
#include <cuda_bf16.h>
#include <cstdint>

#define D        128
#define BLK      1024
#define THREADS  256
#define NROWS    262144

// w = ex2(min(S*C2 + ci + cj, 0)), ci = -||xi||^2*log2e/25.6 (pre-scaled in prep)
#define C2       0.11271055f
#define SQSCALE  (-0.056355275f)

// ---- smem: XOR-swizzled 256B-row tiles ----
#define OFF_XIH  0                     // 64 x 256 = 16K
#define OFF_XIL  16384
#define OFF_W    32768                 // 64 x 256 (128 j-cols bf16)
#define OFF_XJH  49152                 // 128 x 256 = 32K
#define OFF_XJL  81920
#define SM_TOTAL 114688                // 112KB -> 2 CTAs/SM (229376 <= 233472)

// ---------------- global scratch ----------------
__device__ float          g_sq[NROWS];                 // pre-scaled
__device__ __nv_bfloat16  g_xhi[(size_t)NROWS * D];
__device__ __nv_bfloat16  g_xlo[(size_t)NROWS * D];

// ---------------- PTX helpers ----------------
__device__ __forceinline__ uint32_t smem_u32(const void* p) {
    uint32_t a;
    asm("{ .reg .u64 t; cvta.to.shared.u64 t, %1; cvt.u32.u64 %0, t; }" : "=r"(a) : "l"(p));
    return a;
}
__device__ __forceinline__ void cpa16(uint32_t dst, const void* src) {
    asm volatile("cp.async.cg.shared.global [%0], [%1], 16;" :: "r"(dst), "l"(src));
}
#define CP_COMMIT() asm volatile("cp.async.commit_group;" ::: "memory")
#define CP_WAIT0()  asm volatile("cp.async.wait_group 0;" ::: "memory")

__device__ __forceinline__ void ldsm4(uint32_t r[4], uint32_t addr) {
    asm volatile("ldmatrix.sync.aligned.m8n8.x4.shared.b16 {%0,%1,%2,%3}, [%4];"
                 : "=r"(r[0]), "=r"(r[1]), "=r"(r[2]), "=r"(r[3]) : "r"(addr));
}
__device__ __forceinline__ void ldsm4t(uint32_t r[4], uint32_t addr) {
    asm volatile("ldmatrix.sync.aligned.m8n8.x4.trans.shared.b16 {%0,%1,%2,%3}, [%4];"
                 : "=r"(r[0]), "=r"(r[1]), "=r"(r[2]), "=r"(r[3]) : "r"(addr));
}
__device__ __forceinline__ void mma16816(float c[4], const uint32_t a[4],
                                         uint32_t b0, uint32_t b1) {
    asm volatile("mma.sync.aligned.m16n8k16.row.col.f32.bf16.bf16.f32 "
                 "{%0,%1,%2,%3}, {%4,%5,%6,%7}, {%8,%9}, {%0,%1,%2,%3};"
                 : "+f"(c[0]), "+f"(c[1]), "+f"(c[2]), "+f"(c[3])
                 : "r"(a[0]), "r"(a[1]), "r"(a[2]), "r"(a[3]), "r"(b0), "r"(b1));
}
__device__ __forceinline__ float ex2(float e) {
    float r;
    asm("ex2.approx.f32 %0, %1;" : "=f"(r) : "f"(e));
    return r;
}
__device__ __forceinline__ uint32_t bf2u(__nv_bfloat162 h) {
    return *reinterpret_cast<uint32_t*>(&h);
}

// ---------------------------------------------------------------------------
// Prepass: fp32 -> bf16 hi/lo + pre-scaled row norms. One warp per row.
// ---------------------------------------------------------------------------
__global__ __launch_bounds__(256) void prep_kernel(const float4* __restrict__ x) {
    int row = blockIdx.x * 8 + (threadIdx.x >> 5);
    int l   = threadIdx.x & 31;
    float4 v = __ldg(&x[(size_t)row * 32 + l]);
    float s = v.x * v.x + v.y * v.y + v.z * v.z + v.w * v.w;
    #pragma unroll
    for (int o = 16; o; o >>= 1) s += __shfl_xor_sync(0xFFFFFFFFu, s, o);
    if (l == 0) g_sq[row] = s * SQSCALE;
    __nv_bfloat162 h01 = __floats2bfloat162_rn(v.x, v.y);
    __nv_bfloat162 h23 = __floats2bfloat162_rn(v.z, v.w);
    float2 f01 = __bfloat1622float2(h01);
    float2 f23 = __bfloat1622float2(h23);
    __nv_bfloat162 g01 = __floats2bfloat162_rn(v.x - f01.x, v.y - f01.y);
    __nv_bfloat162 g23 = __floats2bfloat162_rn(v.z - f23.x, v.w - f23.y);
    ((uint2*)g_xhi)[(size_t)row * 32 + l] = make_uint2(bf2u(h01), bf2u(h23));
    ((uint2*)g_xlo)[(size_t)row * 32 + l] = make_uint2(bf2u(g01), bf2u(g23));
}

// cp.async a 128x128 bf16 tile pair (hi+lo) into swizzled smem (physical chunk = c16 ^ (row&7))
__device__ __forceinline__ void issue_xj(uint32_t dH, uint32_t dL,
                                         const char* gh, const char* gl, int tid) {
    #pragma unroll
    for (int it = 0; it < 8; ++it) {
        int q   = tid + it * 256;            // 0..2047 16B chunks
        int row = q >> 4, c16 = q & 15;
        uint32_t dsw = (uint32_t)((row << 8) + ((c16 ^ (row & 7)) << 4));
        cpa16(dH + dsw, gh + (size_t)q * 16);
        cpa16(dL + dsw, gl + (size_t)q * 16);
    }
}

// ---------------------------------------------------------------------------
// Fused attention: CTA = 64 i-rows, 2 CTAs/SM; swizzled smem; single Xj buffer.
// Warp grid: wm (0..1) = 32 i-rows; wn (0..3) = 32 j-cols (G1) / 32 d-cols (G2).
// ---------------------------------------------------------------------------
__global__ __launch_bounds__(THREADS, 2)
void attn_kernel(float* __restrict__ out) {
    extern __shared__ char sm[];
    const uint32_t sb = smem_u32(sm);

    const int tid = threadIdx.x;
    const int wid = tid >> 5;
    const int l   = tid & 31;
    const int wm  = wid >> 2;          // 0..1
    const int wn  = wid & 3;           // 0..3
    const int cta  = blockIdx.x;
    const int blkI = cta >> 4, isub = cta & 15;
    const size_t rowbase = (size_t)blkI * BLK;
    const size_t irow0   = rowbase + (size_t)isub * 64;

    const int ph  = l & 7;             // LDSM swizzle phase
    const int rph = (l >> 2) & 7;      // epilogue store phase
    const int cA  = l >> 4;
    const int cB  = (l >> 3) & 1;

    // lane base row offsets (row stride 256B)
    const uint32_t aRow  = (uint32_t)((32 * wm + (l & 15)) << 8);                  // Xi / W A-style
    const uint32_t b1Row = (uint32_t)((32 * wn + (l & 7) + ((l >> 4) << 3)) << 8); // G1 B (+4096/nt2)
    const uint32_t b2Row = (uint32_t)((l & 15) << 8);                              // G2 B trans (+4096/ks)

    const char* ghb = (const char*)(g_xhi + rowbase * D);
    const char* glb = (const char*)(g_xlo + rowbase * D);

    // ---- prologue: Xi tiles via cp.async (64 rows = 1024 chunks each) ----
    {
        const char* gih = (const char*)(g_xhi + irow0 * D);
        const char* gil = (const char*)(g_xlo + irow0 * D);
        #pragma unroll
        for (int it = 0; it < 4; ++it) {
            int q   = tid + it * 256;
            int row = q >> 4, c16 = q & 15;
            uint32_t dsw = (uint32_t)((row << 8) + ((c16 ^ (row & 7)) << 4));
            cpa16(sb + OFF_XIH + dsw, gih + (size_t)q * 16);
            cpa16(sb + OFF_XIL + dsw, gil + (size_t)q * 16);
        }
        CP_COMMIT();
    }

    // pre-scaled i-norms, direct LDG
    float civ[2][2];
    #pragma unroll
    for (int mt = 0; mt < 2; ++mt) {
        civ[mt][0] = __ldg(&g_sq[irow0 + 32 * wm + 16 * mt + (l >> 2)]);
        civ[mt][1] = __ldg(&g_sq[irow0 + 32 * wm + 16 * mt + 8 + (l >> 2)]);
    }

    float acc2[2][4][4];
    #pragma unroll
    for (int mt = 0; mt < 2; ++mt)
        #pragma unroll
        for (int n = 0; n < 4; ++n)
            #pragma unroll
            for (int c = 0; c < 4; ++c) acc2[mt][n][c] = 0.0f;

    for (int jt = 0; jt < 8; ++jt) {
        __syncthreads();   // prev GEMM2's Xj readers done -> Xj writable
        issue_xj(sb + OFF_XJH, sb + OFF_XJL,
                 ghb + (size_t)jt * 32768, glb + (size_t)jt * 32768, tid);
        CP_COMMIT();
        CP_WAIT0();        // (first iter also drains Xi)
        __syncthreads();   // Xj visible

        // ---- GEMM1: S(32x32/warp) = Xi . Xj^T, 3 combos ----
        float acc1[2][4][4];
        #pragma unroll
        for (int mt = 0; mt < 2; ++mt)
            #pragma unroll
            for (int n = 0; n < 4; ++n)
                #pragma unroll
                for (int c = 0; c < 4; ++c) acc1[mt][n][c] = 0.0f;

        #pragma unroll
        for (int ks = 0; ks < 8; ++ks) {
            const uint32_t ca = (uint32_t)(((2 * ks + cA) ^ ph) << 4);
            const uint32_t cb = (uint32_t)(((2 * ks + cB) ^ ph) << 4);
            uint32_t ah[2][4], al[2][4];
            #pragma unroll
            for (int mt = 0; mt < 2; ++mt) {
                ldsm4(ah[mt], sb + OFF_XIH + aRow + mt * 4096 + ca);
                ldsm4(al[mt], sb + OFF_XIL + aRow + mt * 4096 + ca);
            }
            #pragma unroll
            for (int nt2 = 0; nt2 < 2; ++nt2) {
                uint32_t bh[4], bl[4];
                ldsm4(bh, sb + OFF_XJH + b1Row + nt2 * 4096 + cb);
                ldsm4(bl, sb + OFF_XJL + b1Row + nt2 * 4096 + cb);
                #pragma unroll
                for (int mt = 0; mt < 2; ++mt) {
                    mma16816(acc1[mt][2 * nt2],     ah[mt], bh[0], bh[1]);
                    mma16816(acc1[mt][2 * nt2 + 1], ah[mt], bh[2], bh[3]);
                    mma16816(acc1[mt][2 * nt2],     al[mt], bh[0], bh[1]);
                    mma16816(acc1[mt][2 * nt2 + 1], al[mt], bh[2], bh[3]);
                    mma16816(acc1[mt][2 * nt2],     ah[mt], bl[0], bl[1]);
                    mma16816(acc1[mt][2 * nt2 + 1], ah[mt], bl[2], bl[3]);
                }
            }
        }

        // ---- epilogue: w -> swizzled W tile (64 rows x 128 j-cols) ----
        {
            const float2* cjp = (const float2*)(g_sq + rowbase + (size_t)jt * 128);
            #pragma unroll
            for (int n = 0; n < 4; ++n) {
                float2 cj = __ldg(&cjp[16 * wn + 4 * n + (l & 3)]);
                const uint32_t wcol = (uint32_t)((((4 * wn + n) ^ rph) << 4) + ((l & 3) << 2));
                #pragma unroll
                for (int mt = 0; mt < 2; ++mt) {
                    const float* c = acc1[mt][n];
                    float w0 = ex2(fminf(fmaf(c[0], C2, civ[mt][0] + cj.x), 0.0f));
                    float w1 = ex2(fminf(fmaf(c[1], C2, civ[mt][0] + cj.y), 0.0f));
                    float w2 = ex2(fminf(fmaf(c[2], C2, civ[mt][1] + cj.x), 0.0f));
                    float w3 = ex2(fminf(fmaf(c[3], C2, civ[mt][1] + cj.y), 0.0f));
                    const uint32_t wr = (uint32_t)((32 * wm + 16 * mt + (l >> 2)) << 8);
                    *(uint32_t*)(sm + OFF_W + wr + wcol)        = bf2u(__floats2bfloat162_rn(w0, w1));
                    *(uint32_t*)(sm + OFF_W + wr + 2048 + wcol) = bf2u(__floats2bfloat162_rn(w2, w3));
                }
            }
        }
        __syncthreads();   // W complete

        // ---- GEMM2: acc2(32x32/warp) += W . Xj  (2 combos, K=128) ----
        #pragma unroll
        for (int ks = 0; ks < 8; ++ks) {
            const uint32_t ca = (uint32_t)(((2 * ks + cA) ^ ph) << 4);
            uint32_t wh[2][4];
            #pragma unroll
            for (int mt = 0; mt < 2; ++mt)
                ldsm4(wh[mt], sb + OFF_W + aRow + mt * 4096 + ca);
            #pragma unroll
            for (int dp = 0; dp < 2; ++dp) {
                const uint32_t cb2 = (uint32_t)(((4 * wn + 2 * dp + cA) ^ ph) << 4);
                uint32_t bh[4], bl[4];
                ldsm4t(bh, sb + OFF_XJH + b2Row + ks * 4096 + cb2);
                ldsm4t(bl, sb + OFF_XJL + b2Row + ks * 4096 + cb2);
                #pragma unroll
                for (int mt = 0; mt < 2; ++mt) {
                    mma16816(acc2[mt][2 * dp],     wh[mt], bh[0], bh[1]);
                    mma16816(acc2[mt][2 * dp + 1], wh[mt], bh[2], bh[3]);
                    mma16816(acc2[mt][2 * dp],     wh[mt], bl[0], bl[1]);
                    mma16816(acc2[mt][2 * dp + 1], wh[mt], bl[2], bl[3]);
                }
            }
        }
    }

    // ---- write out (scale 1/1024) ----
    const float sc = 1.0f / (float)BLK;
    #pragma unroll
    for (int mt = 0; mt < 2; ++mt) {
        const size_t r0 = irow0 + 32 * wm + 16 * mt + (l >> 2);
        #pragma unroll
        for (int n = 0; n < 4; ++n) {
            const int col = 32 * wn + 8 * n + 2 * (l & 3);
            *(float2*)(out + r0 * D + col)       = make_float2(acc2[mt][n][0] * sc, acc2[mt][n][1] * sc);
            *(float2*)(out + (r0 + 8) * D + col) = make_float2(acc2[mt][n][2] * sc, acc2[mt][n][3] * sc);
        }
    }
}

// ---------------------------------------------------------------------------
extern "C" void kernel_launch(void* const* d_in, const int* in_sizes, int n_in,
                              void* d_out, int out_size) {
    const float* x = (const float*)d_in[0];
    float* out = (float*)d_out;
    const int nrows = in_sizes[0] / D;

    static bool attr_set = false;
    if (!attr_set) {
        cudaFuncSetAttribute(attn_kernel,
                             cudaFuncAttributeMaxDynamicSharedMemorySize, SM_TOTAL);
        attr_set = true;
    }
    prep_kernel<<<nrows / 8, 256>>>((const float4*)x);
    attn_kernel<<<nrows / 64, THREADS, SM_TOTAL>>>(out);
}

// round 13
// speedup vs baseline: 1.8162x; 1.4025x over previous
#include <cuda_runtime.h>
#include <cuda_fp16.h>
#include <cstdint>

#define D        128
#define BLK      1024
#define THREADS  256
#define NROWS    262144

// w = ex2(min(S*C2 + ci + cj, 0)), ci = -||xi||^2*log2e/25.6 (pre-scaled in prep)
#define C2       0.11271055f
#define SQSCALE  (-0.056355275f)

// ---- smem: XOR-swizzled 256B-row tiles ----
#define OFF_XIH  0                     // 64 x 256 = 16K (fp16 hi only)
#define OFF_W    16384                 // 64 x 256 (128 j-cols fp16)
#define OFF_XJH  32768                 // 128 x 256 = 32K
#define OFF_XJL  65536
#define SM_TOTAL 98304                 // 96KB -> 2 CTAs/SM

// ---------------- global scratch ----------------
__device__ float   g_sq[NROWS];                     // pre-scaled
__device__ __half  g_xhi[(size_t)NROWS * D];
__device__ __half  g_xlo[(size_t)NROWS * D];

// ---------------- PTX helpers ----------------
__device__ __forceinline__ uint32_t smem_u32(const void* p) {
    uint32_t a;
    asm("{ .reg .u64 t; cvta.to.shared.u64 t, %1; cvt.u32.u64 %0, t; }" : "=r"(a) : "l"(p));
    return a;
}
__device__ __forceinline__ void cpa16(uint32_t dst, const void* src) {
    asm volatile("cp.async.cg.shared.global [%0], [%1], 16;" :: "r"(dst), "l"(src));
}
#define CP_COMMIT() asm volatile("cp.async.commit_group;" ::: "memory")
#define CP_WAIT0()  asm volatile("cp.async.wait_group 0;" ::: "memory")

__device__ __forceinline__ void ldsm4(uint32_t r[4], uint32_t addr) {
    asm volatile("ldmatrix.sync.aligned.m8n8.x4.shared.b16 {%0,%1,%2,%3}, [%4];"
                 : "=r"(r[0]), "=r"(r[1]), "=r"(r[2]), "=r"(r[3]) : "r"(addr));
}
__device__ __forceinline__ void ldsm4t(uint32_t r[4], uint32_t addr) {
    asm volatile("ldmatrix.sync.aligned.m8n8.x4.trans.shared.b16 {%0,%1,%2,%3}, [%4];"
                 : "=r"(r[0]), "=r"(r[1]), "=r"(r[2]), "=r"(r[3]) : "r"(addr));
}
__device__ __forceinline__ void mma16816(float c[4], const uint32_t a[4],
                                         uint32_t b0, uint32_t b1) {
    asm volatile("mma.sync.aligned.m16n8k16.row.col.f32.f16.f16.f32 "
                 "{%0,%1,%2,%3}, {%4,%5,%6,%7}, {%8,%9}, {%0,%1,%2,%3};"
                 : "+f"(c[0]), "+f"(c[1]), "+f"(c[2]), "+f"(c[3])
                 : "r"(a[0]), "r"(a[1]), "r"(a[2]), "r"(a[3]), "r"(b0), "r"(b1));
}
__device__ __forceinline__ float ex2(float e) {
    float r;
    asm("ex2.approx.f32 %0, %1;" : "=f"(r) : "f"(e));
    return r;
}
__device__ __forceinline__ uint32_t h2u(__half2 h) {
    return *reinterpret_cast<uint32_t*>(&h);
}

// ---------------------------------------------------------------------------
// Prepass: fp32 -> fp16 hi/lo + pre-scaled row norms. One warp per row.
// ---------------------------------------------------------------------------
__global__ __launch_bounds__(256) void prep_kernel(const float4* __restrict__ x) {
    int row = blockIdx.x * 8 + (threadIdx.x >> 5);
    int l   = threadIdx.x & 31;
    float4 v = __ldg(&x[(size_t)row * 32 + l]);
    float s = v.x * v.x + v.y * v.y + v.z * v.z + v.w * v.w;
    #pragma unroll
    for (int o = 16; o; o >>= 1) s += __shfl_xor_sync(0xFFFFFFFFu, s, o);
    if (l == 0) g_sq[row] = s * SQSCALE;
    __half2 h01 = __floats2half2_rn(v.x, v.y);
    __half2 h23 = __floats2half2_rn(v.z, v.w);
    float2 f01 = __half22float2(h01);
    float2 f23 = __half22float2(h23);
    __half2 g01 = __floats2half2_rn(v.x - f01.x, v.y - f01.y);
    __half2 g23 = __floats2half2_rn(v.z - f23.x, v.w - f23.y);
    ((uint2*)g_xhi)[(size_t)row * 32 + l] = make_uint2(h2u(h01), h2u(h23));
    ((uint2*)g_xlo)[(size_t)row * 32 + l] = make_uint2(h2u(g01), h2u(g23));
}

// cp.async a 128x128 fp16 tile pair (hi+lo) into swizzled smem (chunk = c16 ^ (row&7))
__device__ __forceinline__ void issue_xj(uint32_t dH, uint32_t dL,
                                         const char* gh, const char* gl, int tid) {
    #pragma unroll
    for (int it = 0; it < 8; ++it) {
        int q   = tid + it * 256;            // 0..2047 16B chunks
        int row = q >> 4, c16 = q & 15;
        uint32_t dsw = (uint32_t)((row << 8) + ((c16 ^ (row & 7)) << 4));
        cpa16(dH + dsw, gh + (size_t)q * 16);
        cpa16(dL + dsw, gl + (size_t)q * 16);
    }
}

// ---------------------------------------------------------------------------
// Fused attention: CTA = 64 i-rows, 2 CTAs/SM; fp16 split.
// GEMM1 = XiH.XjH^T (1 combo); GEMM2 = W.(XjH+XjL) (2 combos).
// ---------------------------------------------------------------------------
__global__ __launch_bounds__(THREADS, 2)
void attn_kernel(float* __restrict__ out) {
    extern __shared__ char sm[];
    const uint32_t sb = smem_u32(sm);

    const int tid = threadIdx.x;
    const int wid = tid >> 5;
    const int l   = tid & 31;
    const int wm  = wid >> 2;          // 0..1
    const int wn  = wid & 3;           // 0..3
    const int cta  = blockIdx.x;
    const int blkI = cta >> 4, isub = cta & 15;
    const size_t rowbase = (size_t)blkI * BLK;
    const size_t irow0   = rowbase + (size_t)isub * 64;

    const int ph  = l & 7;             // LDSM swizzle phase
    const int rph = (l >> 2) & 7;      // epilogue store phase
    const int cA  = l >> 4;
    const int cB  = (l >> 3) & 1;

    const uint32_t aRow  = (uint32_t)((32 * wm + (l & 15)) << 8);                  // Xi / W A-style
    const uint32_t b1Row = (uint32_t)((32 * wn + (l & 7) + ((l >> 4) << 3)) << 8); // G1 B (+4096/nt2)
    const uint32_t b2Row = (uint32_t)((l & 15) << 8);                              // G2 B trans (+4096/ks)

    const char* ghb = (const char*)(g_xhi + rowbase * D);
    const char* glb = (const char*)(g_xlo + rowbase * D);

    // ---- prologue: XiH tile via cp.async ----
    {
        const char* gih = (const char*)(g_xhi + irow0 * D);
        #pragma unroll
        for (int it = 0; it < 4; ++it) {
            int q   = tid + it * 256;
            int row = q >> 4, c16 = q & 15;
            uint32_t dsw = (uint32_t)((row << 8) + ((c16 ^ (row & 7)) << 4));
            cpa16(sb + OFF_XIH + dsw, gih + (size_t)q * 16);
        }
        CP_COMMIT();
    }

    // pre-scaled i-norms, direct LDG
    float civ[2][2];
    #pragma unroll
    for (int mt = 0; mt < 2; ++mt) {
        civ[mt][0] = __ldg(&g_sq[irow0 + 32 * wm + 16 * mt + (l >> 2)]);
        civ[mt][1] = __ldg(&g_sq[irow0 + 32 * wm + 16 * mt + 8 + (l >> 2)]);
    }

    float acc2[2][4][4];
    #pragma unroll
    for (int mt = 0; mt < 2; ++mt)
        #pragma unroll
        for (int n = 0; n < 4; ++n)
            #pragma unroll
            for (int c = 0; c < 4; ++c) acc2[mt][n][c] = 0.0f;

    for (int jt = 0; jt < 8; ++jt) {
        __syncthreads();   // prev GEMM2's Xj readers done -> Xj writable
        issue_xj(sb + OFF_XJH, sb + OFF_XJL,
                 ghb + (size_t)jt * 32768, glb + (size_t)jt * 32768, tid);
        CP_COMMIT();
        CP_WAIT0();        // (first iter also drains Xi)
        __syncthreads();   // Xj visible

        // ---- GEMM1: S(32x32/warp) = XiH . XjH^T (1 combo) ----
        float acc1[2][4][4];
        #pragma unroll
        for (int mt = 0; mt < 2; ++mt)
            #pragma unroll
            for (int n = 0; n < 4; ++n)
                #pragma unroll
                for (int c = 0; c < 4; ++c) acc1[mt][n][c] = 0.0f;

        #pragma unroll
        for (int ks = 0; ks < 8; ++ks) {
            const uint32_t ca = (uint32_t)(((2 * ks + cA) ^ ph) << 4);
            const uint32_t cb = (uint32_t)(((2 * ks + cB) ^ ph) << 4);
            uint32_t ah[2][4];
            #pragma unroll
            for (int mt = 0; mt < 2; ++mt)
                ldsm4(ah[mt], sb + OFF_XIH + aRow + mt * 4096 + ca);
            #pragma unroll
            for (int nt2 = 0; nt2 < 2; ++nt2) {
                uint32_t bh[4];
                ldsm4(bh, sb + OFF_XJH + b1Row + nt2 * 4096 + cb);
                #pragma unroll
                for (int mt = 0; mt < 2; ++mt) {
                    mma16816(acc1[mt][2 * nt2],     ah[mt], bh[0], bh[1]);
                    mma16816(acc1[mt][2 * nt2 + 1], ah[mt], bh[2], bh[3]);
                }
            }
        }

        // ---- epilogue: w -> swizzled W tile (fp16) ----
        {
            const float2* cjp = (const float2*)(g_sq + rowbase + (size_t)jt * 128);
            #pragma unroll
            for (int n = 0; n < 4; ++n) {
                float2 cj = __ldg(&cjp[16 * wn + 4 * n + (l & 3)]);
                const uint32_t wcol = (uint32_t)((((4 * wn + n) ^ rph) << 4) + ((l & 3) << 2));
                #pragma unroll
                for (int mt = 0; mt < 2; ++mt) {
                    const float* c = acc1[mt][n];
                    float w0 = ex2(fminf(fmaf(c[0], C2, civ[mt][0] + cj.x), 0.0f));
                    float w1 = ex2(fminf(fmaf(c[1], C2, civ[mt][0] + cj.y), 0.0f));
                    float w2 = ex2(fminf(fmaf(c[2], C2, civ[mt][1] + cj.x), 0.0f));
                    float w3 = ex2(fminf(fmaf(c[3], C2, civ[mt][1] + cj.y), 0.0f));
                    const uint32_t wr = (uint32_t)((32 * wm + 16 * mt + (l >> 2)) << 8);
                    *(uint32_t*)(sm + OFF_W + wr + wcol)        = h2u(__floats2half2_rn(w0, w1));
                    *(uint32_t*)(sm + OFF_W + wr + 2048 + wcol) = h2u(__floats2half2_rn(w2, w3));
                }
            }
        }
        __syncthreads();   // W complete

        // ---- GEMM2: acc2(32x32/warp) += W . Xj  (2 combos, K=128) ----
        #pragma unroll
        for (int ks = 0; ks < 8; ++ks) {
            const uint32_t ca = (uint32_t)(((2 * ks + cA) ^ ph) << 4);
            uint32_t wh[2][4];
            #pragma unroll
            for (int mt = 0; mt < 2; ++mt)
                ldsm4(wh[mt], sb + OFF_W + aRow + mt * 4096 + ca);
            #pragma unroll
            for (int dp = 0; dp < 2; ++dp) {
                const uint32_t cb2 = (uint32_t)(((4 * wn + 2 * dp + cA) ^ ph) << 4);
                uint32_t bh[4], bl[4];
                ldsm4t(bh, sb + OFF_XJH + b2Row + ks * 4096 + cb2);
                ldsm4t(bl, sb + OFF_XJL + b2Row + ks * 4096 + cb2);
                #pragma unroll
                for (int mt = 0; mt < 2; ++mt) {
                    mma16816(acc2[mt][2 * dp],     wh[mt], bh[0], bh[1]);
                    mma16816(acc2[mt][2 * dp + 1], wh[mt], bh[2], bh[3]);
                    mma16816(acc2[mt][2 * dp],     wh[mt], bl[0], bl[1]);
                    mma16816(acc2[mt][2 * dp + 1], wh[mt], bl[2], bl[3]);
                }
            }
        }
    }

    // ---- write out (scale 1/1024) ----
    const float sc = 1.0f / (float)BLK;
    #pragma unroll
    for (int mt = 0; mt < 2; ++mt) {
        const size_t r0 = irow0 + 32 * wm + 16 * mt + (l >> 2);
        #pragma unroll
        for (int n = 0; n < 4; ++n) {
            const int col = 32 * wn + 8 * n + 2 * (l & 3);
            *(float2*)(out + r0 * D + col)       = make_float2(acc2[mt][n][0] * sc, acc2[mt][n][1] * sc);
            *(float2*)(out + (r0 + 8) * D + col) = make_float2(acc2[mt][n][2] * sc, acc2[mt][n][3] * sc);
        }
    }
}

// ---------------------------------------------------------------------------
extern "C" void kernel_launch(void* const* d_in, const int* in_sizes, int n_in,
                              void* d_out, int out_size) {
    const float* x = (const float*)d_in[0];
    float* out = (float*)d_out;
    const int nrows = in_sizes[0] / D;

    static bool attr_set = false;
    if (!attr_set) {
        cudaFuncSetAttribute(attn_kernel,
                             cudaFuncAttributeMaxDynamicSharedMemorySize, SM_TOTAL);
        attr_set = true;
    }
    prep_kernel<<<nrows / 8, 256>>>((const float4*)x);
    attn_kernel<<<nrows / 64, THREADS, SM_TOTAL>>>(out);
}